// round 14
// baseline (speedup 1.0000x reference)
#include <cuda_runtime.h>
#include <cuda_bf16.h>
#include <cstdint>

// AttentionLayer: out[b,u] = sum_t softmax_t(tanh(x[b,t,:]·W + b[t])) * x[b,t,u]
// B=256, T=2048, U=512, fp32. Single fused HBM pass (tanh in (-1,1) => exp
// safe without max-subtraction).
// R13 = R8 base with load-issue restructure: after the dot consumes row i's
// registers, the SAME registers are immediately refilled with row i+1's
// demand loads, which then fly during the shfl/tanh/exp chain. The weighted
// accumulation re-reads row i from L1 (just-loaded, guaranteed hit, ~39cyc)
// through a 4-register temp. Zero extra row buffers -> no R3-style spill.

#define B_DIM  256
#define T_DIM  2048
#define U_DIM  512
#define NSPLIT 2                       // T split factor
#define NUNIT  (B_DIM * NSPLIT)        // 512 work units
#define NWARP  8                       // warps per CTA (256 threads)
#define ROWS_PER_UNIT (T_DIM / NSPLIT) // 1024
#define TPW    (ROWS_PER_UNIT / NWARP) // 128 rows per warp

__device__ float        g_acc[NUNIT][U_DIM]; // 1 MB partial weighted sums
__device__ float        g_s[NUNIT];          // partial denominators
__device__ unsigned int g_ticket[B_DIM];     // zero-init; combiner resets

__device__ __forceinline__ float tanh_approx(float v) {
    float r;
    asm("tanh.approx.f32 %0, %1;" : "=f"(r) : "f"(v));
    return r;
}

__global__ __launch_bounds__(256, 4)
void attn_pool_kernel(const float* __restrict__ x,
                      const float* __restrict__ W,
                      const float* __restrict__ bvec,
                      float* __restrict__ out)
{
    __shared__ float sacc[NWARP * U_DIM];   // 16 KB per CTA
    __shared__ float ssum[NWARP];
    __shared__ int   s_last;

    const int unit  = blockIdx.x;           // 0..511
    const int batch = unit >> 1;
    const int half  = unit & 1;
    const int tid   = threadIdx.x;
    const int warp  = tid >> 5;
    const int lane  = tid & 31;

    // Per-lane W slice: lane holds u = c*128 + lane*4 + {0..3}
    float4 wv[4];
#pragma unroll
    for (int c = 0; c < 4; c++)
        wv[c] = reinterpret_cast<const float4*>(W)[c * 32 + lane];

    float4 acc[4];
#pragma unroll
    for (int c = 0; c < 4; c++)
        acc[c] = make_float4(0.f, 0.f, 0.f, 0.f);
    float s = 0.f;

    const float4* xb = reinterpret_cast<const float4*>(
        x + (size_t)batch * T_DIM * U_DIM);

    // Contiguous 128-row slab per warp inside this unit's half of T.
    const int t0 = half * ROWS_PER_UNIT + warp * TPW;

    // rowp = lane address of the row currently held in xv.
    const float4* rowp = xb + (size_t)t0 * 128 + lane;

    // Prologue: row t0 into xv.
    float4 xv[4];
#pragma unroll
    for (int c = 0; c < 4; c++)
        xv[c] = rowp[c * 32];

    for (int i = 0; i < TPW; i++) {
        // 1) Dot with W — consumes xv (row i); afterwards xv is dead.
        float p = 0.f;
#pragma unroll
        for (int c = 0; c < 4; c++)
            p += xv[c].x * wv[c].x + xv[c].y * wv[c].y
               + xv[c].z * wv[c].z + xv[c].w * wv[c].w;

        // 2) Refill xv with row i+1 NOW: these DRAM demand loads fly during
        //    the reduction chain below (WAR on xv after the dot is legal).
        const float4* cur = rowp;           // row i's address (for L1 reload)
        if (i + 1 < TPW) {
            rowp += 128;                    // +2048 B
#pragma unroll
            for (int c = 0; c < 4; c++)
                xv[c] = rowp[c * 32];
        }

        // 3) Load-free chain, overlapped with the in-flight loads.
#pragma unroll
        for (int o = 16; o > 0; o >>= 1)
            p += __shfl_xor_sync(0xffffffffu, p, o);
        const float e = tanh_approx(p + bvec[t0 + i]);
        const float w = __expf(e);          // safe: e in (-1,1)
        s += w;

        // 4) Accumulate row i via L1 re-read (line just fetched -> hit),
        //    4-register temp keeps pressure flat.
#pragma unroll
        for (int c = 0; c < 4; c++) {
            const float4 tmp = __ldca(cur + c * 32);
            acc[c].x += w * tmp.x;
            acc[c].y += w * tmp.y;
            acc[c].z += w * tmp.z;
            acc[c].w += w * tmp.w;
        }
    }

    // Per-warp partials -> shared
#pragma unroll
    for (int c = 0; c < 4; c++)
        reinterpret_cast<float4*>(sacc + warp * U_DIM)[c * 32 + lane] = acc[c];
    if (lane == 0) ssum[warp] = s;
    __syncthreads();

    // Cross-warp reduce -> this unit's global partial (u = tid, tid+256)
    if (tid == 0) {
        float stot = 0.f;
#pragma unroll
        for (int w2 = 0; w2 < NWARP; w2++) stot += ssum[w2];
        g_s[unit] = stot;
    }
#pragma unroll
    for (int k = 0; k < 2; k++) {
        const int u = tid + k * 256;
        float v = 0.f;
#pragma unroll
        for (int w2 = 0; w2 < NWARP; w2++)
            v += sacc[w2 * U_DIM + u];
        g_acc[unit][u] = v;
    }

    // Threadfence-reduction handoff: second CTA of the pair combines.
    __threadfence();
    __syncthreads();
    if (tid == 0)
        s_last = (atomicAdd(&g_ticket[batch], 1u) == 1u);
    __syncthreads();

    if (s_last) {
        __threadfence();                    // acquire partner's partials
        const float stot = g_s[batch * 2] + g_s[batch * 2 + 1];
        const float inv  = 1.0f / stot;
#pragma unroll
        for (int k = 0; k < 2; k++) {
            const int u = tid + k * 256;    // deterministic: fixed add order
            out[(size_t)batch * U_DIM + u] =
                (g_acc[batch * 2][u] + g_acc[batch * 2 + 1][u]) * inv;
        }
        if (tid == 0) g_ticket[batch] = 0;  // reset for next graph replay
    }
}

extern "C" void kernel_launch(void* const* d_in, const int* in_sizes, int n_in,
                              void* d_out, int out_size)
{
    const float* x  = (const float*)d_in[0];   // (256, 2048, 512) f32
    const float* W  = (const float*)d_in[1];   // (512, 1) f32
    const float* bv = (const float*)d_in[2];   // (2048, 1) f32
    float* out = (float*)d_out;                // (256, 512) f32

    attn_pool_kernel<<<NUNIT, 256>>>(x, W, bv, out);
}

// round 15
// speedup vs baseline: 1.1369x; 1.1369x over previous
#include <cuda_runtime.h>
#include <cuda_bf16.h>
#include <cstdint>

// AttentionLayer: out[b,u] = sum_t softmax_t(tanh(x[b,t,:]·W + b[t])) * x[b,t,u]
// B=256, T=2048, U=512, fp32. Single fused HBM pass (tanh in (-1,1) => exp
// safe without max-subtraction).
// R14 = R8 (best measured: balanced 512-unit split, inline threadfence
// combine, W in regs, L2 prefetch of next row) + __ldcs evict-first on the
// x demand loads (x has zero reuse; keep L2 out of the way).
// Duration == DRAM transfer time at ~6.8 TB/s achieved; kernel is at the
// practical bandwidth ceiling.

#define B_DIM  256
#define T_DIM  2048
#define U_DIM  512
#define NSPLIT 2                       // T split factor
#define NUNIT  (B_DIM * NSPLIT)        // 512 work units
#define NWARP  8                       // warps per CTA (256 threads)
#define ROWS_PER_UNIT (T_DIM / NSPLIT) // 1024
#define TPW    (ROWS_PER_UNIT / NWARP) // 128 rows per warp

__device__ float        g_acc[NUNIT][U_DIM]; // 1 MB partial weighted sums
__device__ float        g_s[NUNIT];          // partial denominators
__device__ unsigned int g_ticket[B_DIM];     // zero-initialized; combiner resets

__device__ __forceinline__ void prefetch_l2(const void* p) {
    asm volatile("prefetch.global.L2 [%0];" :: "l"(p));
}

__global__ __launch_bounds__(256, 4)
void attn_pool_kernel(const float* __restrict__ x,
                      const float* __restrict__ W,
                      const float* __restrict__ bvec,
                      float* __restrict__ out)
{
    __shared__ float sacc[NWARP * U_DIM];   // 16 KB per CTA
    __shared__ float ssum[NWARP];
    __shared__ int   s_last;

    const int unit  = blockIdx.x;           // 0..511
    const int batch = unit >> 1;
    const int half  = unit & 1;
    const int tid   = threadIdx.x;
    const int warp  = tid >> 5;
    const int lane  = tid & 31;

    // Per-lane W slice: lane holds u = c*128 + lane*4 + {0..3}
    float4 wv[4];
#pragma unroll
    for (int c = 0; c < 4; c++)
        wv[c] = reinterpret_cast<const float4*>(W)[c * 32 + lane];

    float4 acc[4];
#pragma unroll
    for (int c = 0; c < 4; c++)
        acc[c] = make_float4(0.f, 0.f, 0.f, 0.f);
    float s = 0.f;

    const float4* xb = reinterpret_cast<const float4*>(
        x + (size_t)batch * T_DIM * U_DIM);

    // Contiguous 128-row slab per warp inside this unit's half of T.
    const int t0 = half * ROWS_PER_UNIT + warp * TPW;

    for (int i = 0; i < TPW; i++) {
        const int t = t0 + i;
        const float4* rowp = xb + (size_t)t * 128 + lane;

        // Full 512-float row across the warp: 4x float4 per lane, coalesced,
        // evict-first (zero reuse stream).
        float4 xv[4];
#pragma unroll
        for (int c = 0; c < 4; c++)
            xv[c] = __ldcs(rowp + c * 32);

        // Zero-register L2 prefetch of the next row ([R+imm] addressing).
        if (i + 1 < TPW) {
#pragma unroll
            for (int c = 0; c < 4; c++)
                prefetch_l2(rowp + c * 32 + 128);
        }

        // Dot with W
        float p = 0.f;
#pragma unroll
        for (int c = 0; c < 4; c++)
            p += xv[c].x * wv[c].x + xv[c].y * wv[c].y
               + xv[c].z * wv[c].z + xv[c].w * wv[c].w;

        // Warp butterfly reduction
#pragma unroll
        for (int o = 16; o > 0; o >>= 1)
            p += __shfl_xor_sync(0xffffffffu, p, o);

        const float e = tanhf(p + bvec[t]);
        const float w = __expf(e);          // safe: e in (-1,1)
        s += w;

#pragma unroll
        for (int c = 0; c < 4; c++) {
            acc[c].x += w * xv[c].x;
            acc[c].y += w * xv[c].y;
            acc[c].z += w * xv[c].z;
            acc[c].w += w * xv[c].w;
        }
    }

    // Per-warp partials -> shared
#pragma unroll
    for (int c = 0; c < 4; c++)
        reinterpret_cast<float4*>(sacc + warp * U_DIM)[c * 32 + lane] = acc[c];
    if (lane == 0) ssum[warp] = s;
    __syncthreads();

    // Cross-warp reduce -> this unit's global partial (u = tid, tid+256)
    if (tid == 0) {
        float stot = 0.f;
#pragma unroll
        for (int w2 = 0; w2 < NWARP; w2++) stot += ssum[w2];
        g_s[unit] = stot;
    }
#pragma unroll
    for (int k = 0; k < 2; k++) {
        const int u = tid + k * 256;
        float v = 0.f;
#pragma unroll
        for (int w2 = 0; w2 < NWARP; w2++)
            v += sacc[w2 * U_DIM + u];
        g_acc[unit][u] = v;
    }

    // Threadfence-reduction handoff: second CTA of the pair combines.
    __threadfence();
    __syncthreads();
    if (tid == 0)
        s_last = (atomicAdd(&g_ticket[batch], 1u) == 1u);
    __syncthreads();

    if (s_last) {
        __threadfence();                    // acquire partner's partials
        const float stot = g_s[batch * 2] + g_s[batch * 2 + 1];
        const float inv  = 1.0f / stot;
#pragma unroll
        for (int k = 0; k < 2; k++) {
            const int u = tid + k * 256;    // deterministic: fixed add order
            out[(size_t)batch * U_DIM + u] =
                (g_acc[batch * 2][u] + g_acc[batch * 2 + 1][u]) * inv;
        }
        if (tid == 0) g_ticket[batch] = 0;  // reset for next graph replay
    }
}

extern "C" void kernel_launch(void* const* d_in, const int* in_sizes, int n_in,
                              void* d_out, int out_size)
{
    const float* x  = (const float*)d_in[0];   // (256, 2048, 512) f32
    const float* W  = (const float*)d_in[1];   // (512, 1) f32
    const float* bv = (const float*)d_in[2];   // (2048, 1) f32
    float* out = (float*)d_out;                // (256, 512) f32

    attn_pool_kernel<<<NUNIT, 256>>>(x, W, bv, out);
}

// round 16
// speedup vs baseline: 1.1514x; 1.0128x over previous
#include <cuda_runtime.h>
#include <cuda_bf16.h>
#include <cstdint>

// AttentionLayer: out[b,u] = sum_t softmax_t(tanh(x[b,t,:]·W + b[t])) * x[b,t,u]
// B=256, T=2048, U=512, fp32. Single fused HBM pass (tanh in (-1,1) => exp
// safe without max-subtraction).
// R15 = R8 inner loop, finer balance: T split in quarters -> 1024 units on
// 128-thread CTAs, __launch_bounds__(128,8), all co-resident (1184 capacity).
// Worst-case SM skew 4:3 -> 7:6. Inline threadfence combine over 4 partials.

#define B_DIM  256
#define T_DIM  2048
#define U_DIM  512
#define NSPLIT 4                       // T split factor
#define NUNIT  (B_DIM * NSPLIT)        // 1024 work units
#define NWARP  4                       // warps per CTA (128 threads)
#define ROWS_PER_UNIT (T_DIM / NSPLIT) // 512
#define TPW    (ROWS_PER_UNIT / NWARP) // 128 rows per warp (same as R8)

__device__ float        g_acc[NUNIT][U_DIM]; // 2 MB partial weighted sums
__device__ float        g_s[NUNIT];          // partial denominators
__device__ unsigned int g_ticket[B_DIM];     // zero-initialized; combiner resets

__device__ __forceinline__ void prefetch_l2(const void* p) {
    asm volatile("prefetch.global.L2 [%0];" :: "l"(p));
}

__global__ __launch_bounds__(128, 8)
void attn_pool_kernel(const float* __restrict__ x,
                      const float* __restrict__ W,
                      const float* __restrict__ bvec,
                      float* __restrict__ out)
{
    __shared__ float sacc[NWARP * U_DIM];   // 8 KB per CTA
    __shared__ float ssum[NWARP];
    __shared__ int   s_last;

    const int unit  = blockIdx.x;           // 0..1023
    const int batch = unit >> 2;
    const int quar  = unit & 3;
    const int tid   = threadIdx.x;
    const int warp  = tid >> 5;
    const int lane  = tid & 31;

    // Per-lane W slice: lane holds u = c*128 + lane*4 + {0..3}
    float4 wv[4];
#pragma unroll
    for (int c = 0; c < 4; c++)
        wv[c] = reinterpret_cast<const float4*>(W)[c * 32 + lane];

    float4 acc[4];
#pragma unroll
    for (int c = 0; c < 4; c++)
        acc[c] = make_float4(0.f, 0.f, 0.f, 0.f);
    float s = 0.f;

    const float4* xb = reinterpret_cast<const float4*>(
        x + (size_t)batch * T_DIM * U_DIM);

    // Contiguous 128-row slab per warp inside this unit's quarter of T.
    const int t0 = quar * ROWS_PER_UNIT + warp * TPW;

    for (int i = 0; i < TPW; i++) {
        const int t = t0 + i;
        const float4* rowp = xb + (size_t)t * 128 + lane;

        // Full 512-float row across the warp: 4x float4 per lane, coalesced.
        float4 xv[4];
#pragma unroll
        for (int c = 0; c < 4; c++)
            xv[c] = rowp[c * 32];

        // Zero-register L2 prefetch of the next row ([R+imm] addressing).
        if (i + 1 < TPW) {
#pragma unroll
            for (int c = 0; c < 4; c++)
                prefetch_l2(rowp + c * 32 + 128);
        }

        // Dot with W
        float p = 0.f;
#pragma unroll
        for (int c = 0; c < 4; c++)
            p += xv[c].x * wv[c].x + xv[c].y * wv[c].y
               + xv[c].z * wv[c].z + xv[c].w * wv[c].w;

        // Warp butterfly reduction
#pragma unroll
        for (int o = 16; o > 0; o >>= 1)
            p += __shfl_xor_sync(0xffffffffu, p, o);

        const float e = tanhf(p + bvec[t]);
        const float w = __expf(e);          // safe: e in (-1,1)
        s += w;

#pragma unroll
        for (int c = 0; c < 4; c++) {
            acc[c].x += w * xv[c].x;
            acc[c].y += w * xv[c].y;
            acc[c].z += w * xv[c].z;
            acc[c].w += w * xv[c].w;
        }
    }

    // Per-warp partials -> shared
#pragma unroll
    for (int c = 0; c < 4; c++)
        reinterpret_cast<float4*>(sacc + warp * U_DIM)[c * 32 + lane] = acc[c];
    if (lane == 0) ssum[warp] = s;
    __syncthreads();

    // Cross-warp reduce -> this unit's global partial (u = tid + k*128)
    if (tid == 0) {
        float stot = 0.f;
#pragma unroll
        for (int w2 = 0; w2 < NWARP; w2++) stot += ssum[w2];
        g_s[unit] = stot;
    }
#pragma unroll
    for (int k = 0; k < 4; k++) {
        const int u = tid + k * 128;
        float v = 0.f;
#pragma unroll
        for (int w2 = 0; w2 < NWARP; w2++)
            v += sacc[w2 * U_DIM + u];
        g_acc[unit][u] = v;
    }

    // Threadfence-reduction handoff: last CTA of the 4 combines.
    __threadfence();
    __syncthreads();
    if (tid == 0)
        s_last = (atomicAdd(&g_ticket[batch], 1u) == 3u);
    __syncthreads();

    if (s_last) {
        __threadfence();                    // acquire partners' partials
        float stot = 0.f;
#pragma unroll
        for (int j = 0; j < 4; j++) stot += g_s[batch * 4 + j];
        const float inv = 1.0f / stot;
#pragma unroll
        for (int k = 0; k < 4; k++) {
            const int u = tid + k * 128;
            float v = 0.f;
#pragma unroll
            for (int j = 0; j < 4; j++)     // deterministic: fixed add order
                v += g_acc[batch * 4 + j][u];
            out[(size_t)batch * U_DIM + u] = v * inv;
        }
        if (tid == 0) g_ticket[batch] = 0;  // reset for next graph replay
    }
}

extern "C" void kernel_launch(void* const* d_in, const int* in_sizes, int n_in,
                              void* d_out, int out_size)
{
    const float* x  = (const float*)d_in[0];   // (256, 2048, 512) f32
    const float* W  = (const float*)d_in[1];   // (512, 1) f32
    const float* bv = (const float*)d_in[2];   // (2048, 1) f32
    float* out = (float*)d_out;                // (256, 512) f32

    attn_pool_kernel<<<NUNIT, 128>>>(x, W, bv, out);
}

// round 17
// speedup vs baseline: 1.1643x; 1.0112x over previous
#include <cuda_runtime.h>
#include <cuda_bf16.h>
#include <cstdint>

// AttentionLayer: out[b,u] = sum_t softmax_t(tanh(x[b,t,:]·W + b[t])) * x[b,t,u]
// B=256, T=2048, U=512, fp32. Single fused HBM pass (tanh in (-1,1) => exp
// safe without max-subtraction) -- x (1 GiB) read exactly once.
// FINAL (= R8, best measured 158.2us): balanced 512-unit split (batch x
// half-T) on 256-thread CTAs at occ 4 (all CTAs co-resident, no wave split),
// register-resident W slice, register row buffer, zero-register L2 prefetch
// of the next row, inline threadfence-reduction combine (second CTA of each
// batch pair normalizes). Runtime == DRAM transfer time at ~6.8 TB/s
// achieved; verified local optimum against 8 structural perturbations
// (double-buffer, cp.async, occ-5, tanh.approx, L1 reload, __ldcs, 4-way
// split, finer CTAs) -- all regressed or neutral.

#define B_DIM  256
#define T_DIM  2048
#define U_DIM  512
#define NSPLIT 2                       // T split factor
#define NUNIT  (B_DIM * NSPLIT)        // 512 work units
#define NWARP  8                       // warps per CTA (256 threads)
#define ROWS_PER_UNIT (T_DIM / NSPLIT) // 1024
#define TPW    (ROWS_PER_UNIT / NWARP) // 128 rows per warp

__device__ float        g_acc[NUNIT][U_DIM]; // 1 MB partial weighted sums
__device__ float        g_s[NUNIT];          // partial denominators
__device__ unsigned int g_ticket[B_DIM];     // zero-initialized; combiner resets

__device__ __forceinline__ void prefetch_l2(const void* p) {
    asm volatile("prefetch.global.L2 [%0];" :: "l"(p));
}

__global__ __launch_bounds__(256, 4)
void attn_pool_kernel(const float* __restrict__ x,
                      const float* __restrict__ W,
                      const float* __restrict__ bvec,
                      float* __restrict__ out)
{
    __shared__ float sacc[NWARP * U_DIM];   // 16 KB per CTA
    __shared__ float ssum[NWARP];
    __shared__ int   s_last;

    const int unit  = blockIdx.x;           // 0..511
    const int batch = unit >> 1;
    const int half  = unit & 1;
    const int tid   = threadIdx.x;
    const int warp  = tid >> 5;
    const int lane  = tid & 31;

    // Per-lane W slice: lane holds u = c*128 + lane*4 + {0..3}
    float4 wv[4];
#pragma unroll
    for (int c = 0; c < 4; c++)
        wv[c] = reinterpret_cast<const float4*>(W)[c * 32 + lane];

    float4 acc[4];
#pragma unroll
    for (int c = 0; c < 4; c++)
        acc[c] = make_float4(0.f, 0.f, 0.f, 0.f);
    float s = 0.f;

    const float4* xb = reinterpret_cast<const float4*>(
        x + (size_t)batch * T_DIM * U_DIM);

    // Contiguous 128-row slab per warp inside this unit's half of T.
    const int t0 = half * ROWS_PER_UNIT + warp * TPW;

    for (int i = 0; i < TPW; i++) {
        const int t = t0 + i;
        const float4* rowp = xb + (size_t)t * 128 + lane;

        // Full 512-float row across the warp: 4x float4 per lane, coalesced.
        float4 xv[4];
#pragma unroll
        for (int c = 0; c < 4; c++)
            xv[c] = rowp[c * 32];

        // Zero-register L2 prefetch of the next row ([R+imm] addressing).
        if (i + 1 < TPW) {
#pragma unroll
            for (int c = 0; c < 4; c++)
                prefetch_l2(rowp + c * 32 + 128);
        }

        // Dot with W
        float p = 0.f;
#pragma unroll
        for (int c = 0; c < 4; c++)
            p += xv[c].x * wv[c].x + xv[c].y * wv[c].y
               + xv[c].z * wv[c].z + xv[c].w * wv[c].w;

        // Warp butterfly reduction
#pragma unroll
        for (int o = 16; o > 0; o >>= 1)
            p += __shfl_xor_sync(0xffffffffu, p, o);

        const float e = tanhf(p + bvec[t]);
        const float w = __expf(e);          // safe: e in (-1,1)
        s += w;

#pragma unroll
        for (int c = 0; c < 4; c++) {
            acc[c].x += w * xv[c].x;
            acc[c].y += w * xv[c].y;
            acc[c].z += w * xv[c].z;
            acc[c].w += w * xv[c].w;
        }
    }

    // Per-warp partials -> shared
#pragma unroll
    for (int c = 0; c < 4; c++)
        reinterpret_cast<float4*>(sacc + warp * U_DIM)[c * 32 + lane] = acc[c];
    if (lane == 0) ssum[warp] = s;
    __syncthreads();

    // Cross-warp reduce -> this unit's global partial (u = tid, tid+256)
    if (tid == 0) {
        float stot = 0.f;
#pragma unroll
        for (int w2 = 0; w2 < NWARP; w2++) stot += ssum[w2];
        g_s[unit] = stot;
    }
#pragma unroll
    for (int k = 0; k < 2; k++) {
        const int u = tid + k * 256;
        float v = 0.f;
#pragma unroll
        for (int w2 = 0; w2 < NWARP; w2++)
            v += sacc[w2 * U_DIM + u];
        g_acc[unit][u] = v;
    }

    // Threadfence-reduction handoff: second CTA of the pair combines.
    __threadfence();
    __syncthreads();
    if (tid == 0)
        s_last = (atomicAdd(&g_ticket[batch], 1u) == 1u);
    __syncthreads();

    if (s_last) {
        __threadfence();                    // acquire partner's partials
        const float stot = g_s[batch * 2] + g_s[batch * 2 + 1];
        const float inv  = 1.0f / stot;
#pragma unroll
        for (int k = 0; k < 2; k++) {
            const int u = tid + k * 256;    // deterministic: fixed add order
            out[(size_t)batch * U_DIM + u] =
                (g_acc[batch * 2][u] + g_acc[batch * 2 + 1][u]) * inv;
        }
        if (tid == 0) g_ticket[batch] = 0;  // reset for next graph replay
    }
}

extern "C" void kernel_launch(void* const* d_in, const int* in_sizes, int n_in,
                              void* d_out, int out_size)
{
    const float* x  = (const float*)d_in[0];   // (256, 2048, 512) f32
    const float* W  = (const float*)d_in[1];   // (512, 1) f32
    const float* bv = (const float*)d_in[2];   // (2048, 1) f32
    float* out = (float*)d_out;                // (256, 512) f32

    attn_pool_kernel<<<NUNIT, 256>>>(x, W, bv, out);
}